// round 12
// baseline (speedup 1.0000x reference)
#include <cuda_runtime.h>
#include <cuda_bf16.h>

#define BSZ   512
#define TT    200
#define HID   128
#define GG    512
#define EMBD  100
#define VOC   30000
#define NCLS  9

// g_proj layout: per dir, u64[VOC][256]; slot j of row v = {col j, col j+256}
__device__ float g_proj[2][VOC * GG];
__device__ float g_h[2][BSZ * TT * HID];
// U transposed k-paired: [dir][col][k2], entry = {U[2k2][col], U[2k2+1][col]}
__device__ unsigned long long g_Ut[2][GG * 64];
// BN-folded dense: g_Wp[c][d] (c<9, d<256), g_bp[c]
__device__ float g_Wp[NCLS * 256];
__device__ float g_bp[16];

typedef unsigned long long u64;

__device__ __forceinline__ u64 pk2(float lo, float hi) {
    u64 r; asm("mov.b64 %0, {%1,%2};" : "=l"(r) : "f"(lo), "f"(hi)); return r;
}
__device__ __forceinline__ void upk2(u64 v, float& lo, float& hi) {
    asm("mov.b64 {%0,%1}, %2;" : "=f"(lo), "=f"(hi) : "l"(v));
}
__device__ __forceinline__ u64 fma2(u64 a, u64 b, u64 c) {
    u64 d; asm("fma.rn.f32x2 %0, %1, %2, %3;" : "=l"(d) : "l"(a), "l"(b), "l"(c)); return d;
}
__device__ __forceinline__ float hadd2(u64 v) {
    float lo, hi; upk2(v, lo, hi); return lo + hi;
}
__device__ __forceinline__ float sigf(float x) {
    return __fdividef(1.0f, 1.0f + __expf(-x));
}

// ---------------------------------------------------------------------------
// U transpose: g_Ut[dir][col*64+k2] = {U[2k2][col], U[2k2+1][col]}
// ---------------------------------------------------------------------------
__global__ void utrans_kernel(const float* __restrict__ Uf, const float* __restrict__ Ub)
{
    const int k2  = blockIdx.x & 63;
    const int dir = blockIdx.x >> 6;
    const float* U = dir ? Ub : Uf;
    const int col = threadIdx.x;
    g_Ut[dir][col * 64 + k2] = pk2(U[2 * k2 * GG + col], U[(2 * k2 + 1) * GG + col]);
}

// ---------------------------------------------------------------------------
// Head prep: fold BN into dense.
// ---------------------------------------------------------------------------
__global__ void headprep_kernel(const float* __restrict__ gamma, const float* __restrict__ beta,
                                const float* __restrict__ mean,  const float* __restrict__ var,
                                const float* __restrict__ Wd,    const float* __restrict__ bd)
{
    __shared__ float sc[256], sh[256];
    const int tid = threadIdx.x;
    float rs = rsqrtf(var[tid] + 1e-3f);
    float s  = rs * gamma[tid];
    sc[tid] = s;
    sh[tid] = beta[tid] - mean[tid] * s;
    __syncthreads();
    for (int idx = tid; idx < NCLS * 256; idx += 256) {
        int c = idx >> 8, d = idx & 255;
        g_Wp[idx] = sc[d] * Wd[d * NCLS + c];
    }
    if (tid < NCLS) {
        float acc = bd[tid];
        for (int d = 0; d < 256; d++) acc += sh[d] * Wd[d * NCLS + tid];
        g_bp[tid] = acc;
    }
}

// ---------------------------------------------------------------------------
// proj v4: ALL k in smem up front (one load phase, one sync, 50 k2 straight).
// CTA tile: 128 vocab rows x 32 slots. block 256 = 8 warps; lane = slot,
// warp = 16 rows. smem: W2[50][64] u64 (25600) + e2[50][130] u64 (52000)
// = 77600 -> 2 CTAs/SM. grid = 235 x 8 x 2 = 3760.
// ---------------------------------------------------------------------------
#define EP 130
__global__ __launch_bounds__(256, 2)
void proj_kernel(const float* __restrict__ emb,
                 const float* __restrict__ Wf, const float* __restrict__ bf,
                 const float* __restrict__ Wb, const float* __restrict__ bb)
{
    __shared__ u64 W2[50 * 64];     // [k2][c6]: c6<32 -> col, c6>=32 -> col+256
    __shared__ u64 e2[50 * EP];     // [k2][row]

    const int tid  = threadIdx.x;
    const int lane = tid & 31;
    const int w    = tid >> 5;
    const int bid = blockIdx.x;
    const int dir = bid & 1;
    const int ct  = (bid >> 1) & 7;
    const int rt  = bid >> 4;
    const int colBase = ct * 32;
    const int rowBase = rt * 128;
    const int r0 = w * 16;

    const float* W    = dir ? Wb : Wf;
    const float* bias = dir ? bb : bf;
    u64* out2 = (u64*)g_proj[dir];

    // load W pairs for all 50 k2 (coalesced along cols)
    for (int idx = tid; idx < 3200; idx += 256) {
        int k2 = idx >> 6, c6 = idx & 63;
        int col = colBase + (c6 & 31) + ((c6 >> 5) << 8);
        W2[idx] = pk2(W[(2 * k2) * GG + col], W[(2 * k2 + 1) * GG + col]);
    }
    // load emb pairs for all 128 rows x 50 k2 (row-major gather, coalesced)
    for (int idx = tid; idx < 6400; idx += 256) {
        int r = idx / 50, k2 = idx - r * 50;
        int row = rowBase + r;
        e2[k2 * EP + r] = (row < VOC)
            ? *(const u64*)&emb[row * EMBD + 2 * k2] : 0ULL;
    }
    __syncthreads();

    u64 acc[16][2];
    #pragma unroll
    for (int r = 0; r < 16; r++) { acc[r][0] = 0ULL; acc[r][1] = 0ULL; }

    #pragma unroll 5
    for (int k2 = 0; k2 < 50; k2++) {
        u64 wlo = W2[k2 * 64 + lane];
        u64 whi = W2[k2 * 64 + 32 + lane];
        ulonglong2 E[8];
        #pragma unroll
        for (int j = 0; j < 8; j++)
            E[j] = *(const ulonglong2*)&e2[k2 * EP + r0 + 2 * j];
        #pragma unroll
        for (int j = 0; j < 8; j++) {
            acc[2*j][0]   = fma2(E[j].x, wlo, acc[2*j][0]);
            acc[2*j][1]   = fma2(E[j].x, whi, acc[2*j][1]);
            acc[2*j+1][0] = fma2(E[j].y, wlo, acc[2*j+1][0]);
            acc[2*j+1][1] = fma2(E[j].y, whi, acc[2*j+1][1]);
        }
    }

    const float blo = bias[colBase + lane];
    const float bhi = bias[colBase + lane + 256];
    #pragma unroll
    for (int r = 0; r < 16; r++) {
        int row = rowBase + r0 + r;
        if (row < VOC) {
            float zlo = hadd2(acc[r][0]) + blo;
            float zhi = hadd2(acc[r][1]) + bhi;
            out2[(size_t)row * 256 + colBase + lane] = pk2(zlo, zhi);
        }
    }
}

// ---------------------------------------------------------------------------
// Persistent LSTM v5: 512 threads (4 warps/SMSP). thread (p = tid&255,
// rg = tid>>8) owns cols {p, p+256} x rows 4rg..4rg+3. p<128 -> {i_m, g_m},
// p>=128 -> {f_m, o_m}, m = p&127. Gate exchange: 1 STS.128 + 1 LDS.128.
// U: k2 0..49 smem [col][50], k2 50..63 in regs (2 cols x 14).
// smem: Up2 204800 | hbuf[2][8][64] 8192 | ex[2][256][2] 8192 | tcache 6400
//       = 227584
// ---------------------------------------------------------------------------
#define KS2 50
__global__ __launch_bounds__(512, 1)
void lstm_kernel(const int* __restrict__ tokens)
{
    extern __shared__ char sm_raw[];
    u64* Up2    = (u64*)sm_raw;                    // [col][k2] stride 50
    u64* hbuf   = (u64*)(sm_raw + 204800);         // [buf][row][k2]
    u64* ex     = (u64*)(sm_raw + 212992);         // [rg][p][2]
    int* tcache = (int*)(sm_raw + 221184);

    const int tid = threadIdx.x;
    const int dir = blockIdx.x >> 6;
    const int b0  = (blockIdx.x & 63) * 8;
    const int p   = tid & 255;
    const int rg  = tid >> 8;
    const int m   = p & 127;
    const u64* Ut = g_Ut[dir];
    const u64* proju = (const u64*)g_proj[dir];
    float* hout = g_h[dir];

    // smem U: k2 0..49 of every column
    for (int idx = tid; idx < GG * KS2; idx += 512) {
        int col = idx / KS2, k2 = idx - col * KS2;
        Up2[idx] = Ut[col * 64 + k2];
    }
    // reg U tail: k2 50..63 for this thread's 2 columns
    u64 urA[14], urB[14];
    #pragma unroll
    for (int i = 0; i < 14; i++) {
        urA[i] = Ut[p * 64 + KS2 + i];
        urB[i] = Ut[(p + 256) * 64 + KS2 + i];
    }
    for (int idx = tid; idx < 8 * TT; idx += 512) {
        int r = idx / TT, t = idx % TT;
        tcache[idx] = tokens[(b0 + r) * TT + t];
    }
    hbuf[tid] = 0ULL;
    hbuf[tid + 512] = 0ULL;
    __syncthreads();

    // xz prefetch: slot p of this thread's 4 rows
    u64 xn[4];
    {
        int t0 = dir ? (TT - 1) : 0;
        #pragma unroll
        for (int rr = 0; rr < 4; rr++)
            xn[rr] = proju[(size_t)tcache[(4 * rg + rr) * TT + t0] * 256 + p];
    }

    const int own0 = (p < 128) ? 0 : 2;    // local rows owned for epilogue
    float cst0 = 0.0f, cst1 = 0.0f;

    for (int s = 0; s < TT; s++) {
        const int t = dir ? (TT - 1 - s) : s;
        const u64* hread = hbuf + (s & 1) * 512;
        u64* hwrite      = hbuf + ((s + 1) & 1) * 512;

        // acc init: lo-half = xz, hi = 0
        u64 aA[4], aB[4];
        #pragma unroll
        for (int rr = 0; rr < 4; rr++) {
            float zl, zh;
            upk2(xn[rr], zl, zh);
            aA[rr] = pk2(zl, 0.0f);
            aB[rr] = pk2(zh, 0.0f);
        }
        // prefetch next step's xz (hidden under the matmul)
        {
            int sn = (s + 1 < TT) ? (s + 1) : s;
            int tn = dir ? (TT - 1 - sn) : sn;
            #pragma unroll
            for (int rr = 0; rr < 4; rr++)
                xn[rr] = proju[(size_t)tcache[(4 * rg + rr) * TT + tn] * 256 + p];
        }

        // smem U: 25 groups of 2 k2 (4 k each)
        #pragma unroll 5
        for (int g = 0; g < 25; g++) {
            const int k2 = 2 * g;
            ulonglong2 UA = *(const ulonglong2*)&Up2[p * KS2 + k2];
            ulonglong2 UB = *(const ulonglong2*)&Up2[(p + 256) * KS2 + k2];
            ulonglong2 H0 = *(const ulonglong2*)&hread[(4 * rg + 0) * 64 + k2];
            ulonglong2 H1 = *(const ulonglong2*)&hread[(4 * rg + 1) * 64 + k2];
            ulonglong2 H2 = *(const ulonglong2*)&hread[(4 * rg + 2) * 64 + k2];
            ulonglong2 H3 = *(const ulonglong2*)&hread[(4 * rg + 3) * 64 + k2];
            aA[0] = fma2(H0.x, UA.x, aA[0]); aA[0] = fma2(H0.y, UA.y, aA[0]);
            aA[1] = fma2(H1.x, UA.x, aA[1]); aA[1] = fma2(H1.y, UA.y, aA[1]);
            aA[2] = fma2(H2.x, UA.x, aA[2]); aA[2] = fma2(H2.y, UA.y, aA[2]);
            aA[3] = fma2(H3.x, UA.x, aA[3]); aA[3] = fma2(H3.y, UA.y, aA[3]);
            aB[0] = fma2(H0.x, UB.x, aB[0]); aB[0] = fma2(H0.y, UB.y, aB[0]);
            aB[1] = fma2(H1.x, UB.x, aB[1]); aB[1] = fma2(H1.y, UB.y, aB[1]);
            aB[2] = fma2(H2.x, UB.x, aB[2]); aB[2] = fma2(H2.y, UB.y, aB[2]);
            aB[3] = fma2(H3.x, UB.x, aB[3]); aB[3] = fma2(H3.y, UB.y, aB[3]);
        }
        // reg U tail: 7 groups of 2 k2
        #pragma unroll
        for (int g = 0; g < 7; g++) {
            const int k2 = KS2 + 2 * g;
            u64 uA0 = urA[2 * g], uA1 = urA[2 * g + 1];
            u64 uB0 = urB[2 * g], uB1 = urB[2 * g + 1];
            ulonglong2 H0 = *(const ulonglong2*)&hread[(4 * rg + 0) * 64 + k2];
            ulonglong2 H1 = *(const ulonglong2*)&hread[(4 * rg + 1) * 64 + k2];
            ulonglong2 H2 = *(const ulonglong2*)&hread[(4 * rg + 2) * 64 + k2];
            ulonglong2 H3 = *(const ulonglong2*)&hread[(4 * rg + 3) * 64 + k2];
            aA[0] = fma2(H0.x, uA0, aA[0]); aA[0] = fma2(H0.y, uA1, aA[0]);
            aA[1] = fma2(H1.x, uA0, aA[1]); aA[1] = fma2(H1.y, uA1, aA[1]);
            aA[2] = fma2(H2.x, uA0, aA[2]); aA[2] = fma2(H2.y, uA1, aA[2]);
            aA[3] = fma2(H3.x, uA0, aA[3]); aA[3] = fma2(H3.y, uA1, aA[3]);
            aB[0] = fma2(H0.x, uB0, aB[0]); aB[0] = fma2(H0.y, uB1, aB[0]);
            aB[1] = fma2(H1.x, uB0, aB[1]); aB[1] = fma2(H1.y, uB1, aB[1]);
            aB[2] = fma2(H2.x, uB0, aB[2]); aB[2] = fma2(H2.y, uB1, aB[2]);
            aB[3] = fma2(H3.x, uB0, aB[3]); aB[3] = fma2(H3.y, uB1, aB[3]);
        }

        // finalize gates for all 4 local rows
        float g1[4], g2[4];
        #pragma unroll
        for (int rr = 0; rr < 4; rr++) {
            g1[rr] = hadd2(aA[rr]);
            g2[rr] = hadd2(aB[rr]);
        }

        // ship the 2 non-owned rows to partner (one STS.128)
        {
            const int sh0 = own0 ^ 2;
            ulonglong2 pay;
            pay.x = pk2(g1[sh0],     g2[sh0]);
            pay.y = pk2(g1[sh0 + 1], g2[sh0 + 1]);
            *(ulonglong2*)&ex[(rg * 256 + p) * 2] = pay;
        }
        __syncthreads();

        // epilogue: own 2 rows, all 4 gates now available
        {
            ulonglong2 P = *(const ulonglong2*)&ex[(rg * 256 + (p ^ 128)) * 2];
            u64 pv[2] = {P.x, P.y};
            float cl[2] = {cst0, cst1};
            #pragma unroll
            for (int k = 0; k < 2; k++) {
                int o = own0 + k;
                float p1, p2;
                upk2(pv[k], p1, p2);
                float zi, zf, zg, zo;
                if (p < 128) { zi = g1[o]; zg = g2[o]; zf = p1; zo = p2; }
                else         { zf = g1[o]; zo = g2[o]; zi = p1; zg = p2; }
                float ii = sigf(zi);
                float ff = sigf(zf);
                float gg = fmaxf(zg, 0.0f);
                float oo = sigf(zo);
                float c  = ff * cl[k] + ii * gg;
                cl[k] = c;
                float h = oo * fmaxf(c, 0.0f);
                int row = 4 * rg + o;
                ((float*)&hwrite[row * 64])[m] = h;
                hout[((size_t)(b0 + row) * TT + t) * HID + m] = h;
            }
            cst0 = cl[0];
            cst1 = cl[1];
        }
        __syncthreads();
    }
}

// ---------------------------------------------------------------------------
// Head v2 (unchanged): BN pre-folded, transposed float4 weights.
// ---------------------------------------------------------------------------
__global__ __launch_bounds__(256, 4)
void head_kernel(float* __restrict__ out)
{
    __shared__ float4 Wt4[NCLS][64];
    __shared__ float bsm[NCLS];

    const int tid = threadIdx.x;
    for (int idx = tid; idx < NCLS * 64; idx += 256)
        ((float4*)Wt4)[idx] = ((const float4*)g_Wp)[idx];
    if (tid < NCLS) bsm[tid] = g_bp[tid];
    __syncthreads();

    const int wid  = tid >> 5;
    const int lane = tid & 31;
    const int pos  = blockIdx.x * 8 + wid;

    float4 hf = *(const float4*)&g_h[0][(size_t)pos * HID + lane * 4];
    float4 hb = *(const float4*)&g_h[1][(size_t)pos * HID + lane * 4];

    float acc[NCLS];
    #pragma unroll
    for (int c = 0; c < NCLS; c++) {
        float4 w0 = Wt4[c][lane];
        float4 w1 = Wt4[c][32 + lane];
        float s = hf.x * w0.x + hf.y * w0.y + hf.z * w0.z + hf.w * w0.w;
        s += hb.x * w1.x + hb.y * w1.y + hb.z * w1.z + hb.w * w1.w;
        acc[c] = s;
    }
    #pragma unroll
    for (int off = 16; off >= 1; off >>= 1) {
        #pragma unroll
        for (int c = 0; c < NCLS; c++)
            acc[c] += __shfl_xor_sync(0xFFFFFFFFu, acc[c], off);
    }

    if (lane == 0) {
        float z[NCLS], mx = -1e30f;
        #pragma unroll
        for (int c = 0; c < NCLS; c++) { z[c] = acc[c] + bsm[c]; mx = fmaxf(mx, z[c]); }
        float sum = 0.0f;
        #pragma unroll
        for (int c = 0; c < NCLS; c++) { z[c] = __expf(z[c] - mx); sum += z[c]; }
        float inv = __fdividef(1.0f, sum);
        #pragma unroll
        for (int c = 0; c < NCLS; c++) out[(size_t)pos * NCLS + c] = z[c] * inv;
    }
}

extern "C" void kernel_launch(void* const* d_in, const int* in_sizes, int n_in,
                              void* d_out, int out_size)
{
    const int*   tokens = (const int*)d_in[0];
    const float* emb    = (const float*)d_in[1];
    const float* Wf     = (const float*)d_in[2];
    const float* Uf     = (const float*)d_in[3];
    const float* bf     = (const float*)d_in[4];
    const float* Wb     = (const float*)d_in[5];
    const float* Ub     = (const float*)d_in[6];
    const float* bb     = (const float*)d_in[7];
    const float* gamma  = (const float*)d_in[8];
    const float* beta   = (const float*)d_in[9];
    const float* mmean  = (const float*)d_in[10];
    const float* mvar   = (const float*)d_in[11];
    const float* Wd     = (const float*)d_in[12];
    const float* bd     = (const float*)d_in[13];
    float* out = (float*)d_out;

    static bool attr_done = false;
    if (!attr_done) {
        cudaFuncSetAttribute(lstm_kernel, cudaFuncAttributeMaxDynamicSharedMemorySize, 227584);
        attr_done = true;
    }

    utrans_kernel<<<128, 512>>>(Uf, Ub);
    headprep_kernel<<<1, 256>>>(gamma, beta, mmean, mvar, Wd, bd);
    proj_kernel<<<235 * 8 * 2, 256>>>(emb, Wf, bf, Wb, bb);
    lstm_kernel<<<128, 512, 227584>>>(tokens);
    head_kernel<<<BSZ * TT / 8, 256>>>(out);
}

// round 13
// speedup vs baseline: 1.1872x; 1.1872x over previous
#include <cuda_runtime.h>
#include <cuda_bf16.h>

#define BSZ   512
#define TT    200
#define HID   128
#define GG    512
#define EMBD  100
#define VOC   30000
#define NCLS  9

// g_proj layout: per dir, u64[VOC][256]; slot j of row v = {col j, col j+256}
__device__ float g_proj[2][VOC * GG];
__device__ float g_h[2][BSZ * TT * HID];
// U transposed k-paired: [dir][col][k2], entry = {U[2k2][col], U[2k2+1][col]}
__device__ unsigned long long g_Ut[2][GG * 64];
// BN-folded dense: g_Wp[c][d] (c<9, d<256), g_bp[c]
__device__ float g_Wp[NCLS * 256];
__device__ float g_bp[16];

typedef unsigned long long u64;

__device__ __forceinline__ u64 pk2(float lo, float hi) {
    u64 r; asm("mov.b64 %0, {%1,%2};" : "=l"(r) : "f"(lo), "f"(hi)); return r;
}
__device__ __forceinline__ void upk2(u64 v, float& lo, float& hi) {
    asm("mov.b64 {%0,%1}, %2;" : "=f"(lo), "=f"(hi) : "l"(v));
}
__device__ __forceinline__ u64 fma2(u64 a, u64 b, u64 c) {
    u64 d; asm("fma.rn.f32x2 %0, %1, %2, %3;" : "=l"(d) : "l"(a), "l"(b), "l"(c)); return d;
}
__device__ __forceinline__ float hadd2(u64 v) {
    float lo, hi; upk2(v, lo, hi); return lo + hi;
}
__device__ __forceinline__ float sigf(float x) {
    return __fdividef(1.0f, 1.0f + __expf(-x));
}

// ---------------------------------------------------------------------------
// U transpose: g_Ut[dir][col*64+k2] = {U[2k2][col], U[2k2+1][col]}
// ---------------------------------------------------------------------------
__global__ void utrans_kernel(const float* __restrict__ Uf, const float* __restrict__ Ub)
{
    const int k2  = blockIdx.x & 63;
    const int dir = blockIdx.x >> 6;
    const float* U = dir ? Ub : Uf;
    const int col = threadIdx.x;
    g_Ut[dir][col * 64 + k2] = pk2(U[2 * k2 * GG + col], U[(2 * k2 + 1) * GG + col]);
}

// ---------------------------------------------------------------------------
// Head prep: fold BN into dense.
// ---------------------------------------------------------------------------
__global__ void headprep_kernel(const float* __restrict__ gamma, const float* __restrict__ beta,
                                const float* __restrict__ mean,  const float* __restrict__ var,
                                const float* __restrict__ Wd,    const float* __restrict__ bd)
{
    __shared__ float sc[256], sh[256];
    const int tid = threadIdx.x;
    float rs = rsqrtf(var[tid] + 1e-3f);
    float s  = rs * gamma[tid];
    sc[tid] = s;
    sh[tid] = beta[tid] - mean[tid] * s;
    __syncthreads();
    for (int idx = tid; idx < NCLS * 256; idx += 256) {
        int c = idx >> 8, d = idx & 255;
        g_Wp[idx] = sc[d] * Wd[d * NCLS + c];
    }
    if (tid < NCLS) {
        float acc = bd[tid];
        for (int d = 0; d < 256; d++) acc += sh[d] * Wd[d * NCLS + tid];
        g_bp[tid] = acc;
    }
}

// ---------------------------------------------------------------------------
// proj v4 (kept from R12): ALL k in smem up front, one sync, 50 k2 straight.
// CTA tile: 128 vocab rows x 32 slots. block 256 = 8 warps; lane = slot,
// warp = 16 rows. smem 77600B -> 2 CTAs/SM. grid = 235 x 8 x 2 = 3760.
// ---------------------------------------------------------------------------
#define EP 130
__global__ __launch_bounds__(256, 2)
void proj_kernel(const float* __restrict__ emb,
                 const float* __restrict__ Wf, const float* __restrict__ bf,
                 const float* __restrict__ Wb, const float* __restrict__ bb)
{
    __shared__ u64 W2[50 * 64];     // [k2][c6]: c6<32 -> col, c6>=32 -> col+256
    __shared__ u64 e2[50 * EP];     // [k2][row]

    const int tid  = threadIdx.x;
    const int lane = tid & 31;
    const int w    = tid >> 5;
    const int bid = blockIdx.x;
    const int dir = bid & 1;
    const int ct  = (bid >> 1) & 7;
    const int rt  = bid >> 4;
    const int colBase = ct * 32;
    const int rowBase = rt * 128;
    const int r0 = w * 16;

    const float* W    = dir ? Wb : Wf;
    const float* bias = dir ? bb : bf;
    u64* out2 = (u64*)g_proj[dir];

    for (int idx = tid; idx < 3200; idx += 256) {
        int k2 = idx >> 6, c6 = idx & 63;
        int col = colBase + (c6 & 31) + ((c6 >> 5) << 8);
        W2[idx] = pk2(W[(2 * k2) * GG + col], W[(2 * k2 + 1) * GG + col]);
    }
    for (int idx = tid; idx < 6400; idx += 256) {
        int r = idx / 50, k2 = idx - r * 50;
        int row = rowBase + r;
        e2[k2 * EP + r] = (row < VOC)
            ? *(const u64*)&emb[row * EMBD + 2 * k2] : 0ULL;
    }
    __syncthreads();

    u64 acc[16][2];
    #pragma unroll
    for (int r = 0; r < 16; r++) { acc[r][0] = 0ULL; acc[r][1] = 0ULL; }

    #pragma unroll 5
    for (int k2 = 0; k2 < 50; k2++) {
        u64 wlo = W2[k2 * 64 + lane];
        u64 whi = W2[k2 * 64 + 32 + lane];
        ulonglong2 E[8];
        #pragma unroll
        for (int j = 0; j < 8; j++)
            E[j] = *(const ulonglong2*)&e2[k2 * EP + r0 + 2 * j];
        #pragma unroll
        for (int j = 0; j < 8; j++) {
            acc[2*j][0]   = fma2(E[j].x, wlo, acc[2*j][0]);
            acc[2*j][1]   = fma2(E[j].x, whi, acc[2*j][1]);
            acc[2*j+1][0] = fma2(E[j].y, wlo, acc[2*j+1][0]);
            acc[2*j+1][1] = fma2(E[j].y, whi, acc[2*j+1][1]);
        }
    }

    const float blo = bias[colBase + lane];
    const float bhi = bias[colBase + lane + 256];
    #pragma unroll
    for (int r = 0; r < 16; r++) {
        int row = rowBase + r0 + r;
        if (row < VOC) {
            float zlo = hadd2(acc[r][0]) + blo;
            float zhi = hadd2(acc[r][1]) + bhi;
            out2[(size_t)row * 256 + colBase + lane] = pk2(zlo, zhi);
        }
    }
}

// ---------------------------------------------------------------------------
// Persistent LSTM v3 (exact revert — 738us, proven x3). grid 128 = 2 dirs x
// 64 chunks of 8 batch rows. block 256; thread (m = tid&127, rg = tid>>7)
// owns gate cols {m, m+128, m+256, m+384} x rows 4rg..4rg+3.
// U: k2 0..49 smem [col][50], k2 50..63 regs. 1 barrier/step, dbl-buf h.
// ---------------------------------------------------------------------------
#define KS2 50
__global__ __launch_bounds__(256, 1)
void lstm_kernel(const int* __restrict__ tokens)
{
    extern __shared__ char sm_raw[];
    u64* Up2    = (u64*)sm_raw;                    // [col][k2] stride 50
    u64* hbuf   = (u64*)(sm_raw + 204800);         // [buf][row*64+k2]
    int* tcache = (int*)(sm_raw + 212992);

    const int tid = threadIdx.x;
    const int dir = blockIdx.x >> 6;
    const int b0  = (blockIdx.x & 63) * 8;
    const int m   = tid & 127;
    const int rg  = tid >> 7;
    const u64* Ut = g_Ut[dir];
    const u64* proju = (const u64*)g_proj[dir];
    float* hout = g_h[dir];

    for (int idx = tid; idx < GG * KS2; idx += 256) {
        int col = idx / KS2, k2 = idx - col * KS2;
        Up2[idx] = Ut[col * 64 + k2];
    }
    u64 ur[4][14];
    #pragma unroll
    for (int c = 0; c < 4; c++) {
        const u64* src = &Ut[(m + 128 * c) * 64 + KS2];
        #pragma unroll
        for (int i = 0; i < 14; i++) ur[c][i] = src[i];
    }
    for (int idx = tid; idx < 8 * TT; idx += 256) {
        int r = idx / TT, t = idx % TT;
        tcache[idx] = tokens[(b0 + r) * TT + t];
    }
    hbuf[tid] = 0ULL;
    hbuf[tid + 256] = 0ULL;
    hbuf[tid + 512] = 0ULL;
    hbuf[tid + 768] = 0ULL;
    __syncthreads();

    u64 xA[4], xB[4];
    {
        int t0 = dir ? (TT - 1) : 0;
        #pragma unroll
        for (int rr = 0; rr < 4; rr++) {
            int tok = tcache[(4 * rg + rr) * TT + t0];
            xA[rr] = proju[(size_t)tok * 256 + m];
            xB[rr] = proju[(size_t)tok * 256 + m + 128];
        }
    }

    float cst[4] = {0.f, 0.f, 0.f, 0.f};

    for (int s = 0; s < TT; s++) {
        const int t = dir ? (TT - 1 - s) : s;
        const u64* hread = hbuf + (s & 1) * 512;
        u64* hwrite      = hbuf + ((s + 1) & 1) * 512;

        u64 a[4][4];
        #pragma unroll
        for (int rr = 0; rr < 4; rr++) {
            float xi, xg, xf, xo;
            upk2(xA[rr], xi, xg);
            upk2(xB[rr], xf, xo);
            a[rr][0] = pk2(xi, 0.0f);
            a[rr][1] = pk2(xf, 0.0f);
            a[rr][2] = pk2(xg, 0.0f);
            a[rr][3] = pk2(xo, 0.0f);
        }
        {
            int sn = (s + 1 < TT) ? (s + 1) : s;
            int tn = dir ? (TT - 1 - sn) : sn;
            #pragma unroll
            for (int rr = 0; rr < 4; rr++) {
                int tok = tcache[(4 * rg + rr) * TT + tn];
                xA[rr] = proju[(size_t)tok * 256 + m];
                xB[rr] = proju[(size_t)tok * 256 + m + 128];
            }
        }

        #pragma unroll 5
        for (int g = 0; g < 25; g++) {
            const int k2 = 2 * g;
            ulonglong2 H0 = *(const ulonglong2*)&hread[(4 * rg + 0) * 64 + k2];
            ulonglong2 H1 = *(const ulonglong2*)&hread[(4 * rg + 1) * 64 + k2];
            ulonglong2 H2 = *(const ulonglong2*)&hread[(4 * rg + 2) * 64 + k2];
            ulonglong2 H3 = *(const ulonglong2*)&hread[(4 * rg + 3) * 64 + k2];
            #pragma unroll
            for (int c = 0; c < 4; c++) {
                ulonglong2 U = *(const ulonglong2*)&Up2[(m + 128 * c) * KS2 + k2];
                a[0][c] = fma2(H0.x, U.x, a[0][c]); a[0][c] = fma2(H0.y, U.y, a[0][c]);
                a[1][c] = fma2(H1.x, U.x, a[1][c]); a[1][c] = fma2(H1.y, U.y, a[1][c]);
                a[2][c] = fma2(H2.x, U.x, a[2][c]); a[2][c] = fma2(H2.y, U.y, a[2][c]);
                a[3][c] = fma2(H3.x, U.x, a[3][c]); a[3][c] = fma2(H3.y, U.y, a[3][c]);
            }
        }
        #pragma unroll
        for (int g = 0; g < 7; g++) {
            const int k2 = KS2 + 2 * g;
            ulonglong2 H0 = *(const ulonglong2*)&hread[(4 * rg + 0) * 64 + k2];
            ulonglong2 H1 = *(const ulonglong2*)&hread[(4 * rg + 1) * 64 + k2];
            ulonglong2 H2 = *(const ulonglong2*)&hread[(4 * rg + 2) * 64 + k2];
            ulonglong2 H3 = *(const ulonglong2*)&hread[(4 * rg + 3) * 64 + k2];
            #pragma unroll
            for (int c = 0; c < 4; c++) {
                u64 u0 = ur[c][2 * g], u1 = ur[c][2 * g + 1];
                a[0][c] = fma2(H0.x, u0, a[0][c]); a[0][c] = fma2(H0.y, u1, a[0][c]);
                a[1][c] = fma2(H1.x, u0, a[1][c]); a[1][c] = fma2(H1.y, u1, a[1][c]);
                a[2][c] = fma2(H2.x, u0, a[2][c]); a[2][c] = fma2(H2.y, u1, a[2][c]);
                a[3][c] = fma2(H3.x, u0, a[3][c]); a[3][c] = fma2(H3.y, u1, a[3][c]);
            }
        }

        #pragma unroll
        for (int rr = 0; rr < 4; rr++) {
            float zi = hadd2(a[rr][0]);
            float zf = hadd2(a[rr][1]);
            float zg = hadd2(a[rr][2]);
            float zo = hadd2(a[rr][3]);
            float ii = sigf(zi);
            float ff = sigf(zf);
            float gg = fmaxf(zg, 0.0f);
            float oo = sigf(zo);
            float c  = ff * cst[rr] + ii * gg;
            cst[rr] = c;
            float h = oo * fmaxf(c, 0.0f);
            ((float*)&hwrite[(4 * rg + rr) * 64])[m] = h;
            hout[((size_t)(b0 + 4 * rg + rr) * TT + t) * HID + m] = h;
        }
        __syncthreads();
    }
}

// ---------------------------------------------------------------------------
// Head v2 (unchanged): BN pre-folded, transposed float4 weights.
// ---------------------------------------------------------------------------
__global__ __launch_bounds__(256, 4)
void head_kernel(float* __restrict__ out)
{
    __shared__ float4 Wt4[NCLS][64];
    __shared__ float bsm[NCLS];

    const int tid = threadIdx.x;
    for (int idx = tid; idx < NCLS * 64; idx += 256)
        ((float4*)Wt4)[idx] = ((const float4*)g_Wp)[idx];
    if (tid < NCLS) bsm[tid] = g_bp[tid];
    __syncthreads();

    const int wid  = tid >> 5;
    const int lane = tid & 31;
    const int pos  = blockIdx.x * 8 + wid;

    float4 hf = *(const float4*)&g_h[0][(size_t)pos * HID + lane * 4];
    float4 hb = *(const float4*)&g_h[1][(size_t)pos * HID + lane * 4];

    float acc[NCLS];
    #pragma unroll
    for (int c = 0; c < NCLS; c++) {
        float4 w0 = Wt4[c][lane];
        float4 w1 = Wt4[c][32 + lane];
        float s = hf.x * w0.x + hf.y * w0.y + hf.z * w0.z + hf.w * w0.w;
        s += hb.x * w1.x + hb.y * w1.y + hb.z * w1.z + hb.w * w1.w;
        acc[c] = s;
    }
    #pragma unroll
    for (int off = 16; off >= 1; off >>= 1) {
        #pragma unroll
        for (int c = 0; c < NCLS; c++)
            acc[c] += __shfl_xor_sync(0xFFFFFFFFu, acc[c], off);
    }

    if (lane == 0) {
        float z[NCLS], mx = -1e30f;
        #pragma unroll
        for (int c = 0; c < NCLS; c++) { z[c] = acc[c] + bsm[c]; mx = fmaxf(mx, z[c]); }
        float sum = 0.0f;
        #pragma unroll
        for (int c = 0; c < NCLS; c++) { z[c] = __expf(z[c] - mx); sum += z[c]; }
        float inv = __fdividef(1.0f, sum);
        #pragma unroll
        for (int c = 0; c < NCLS; c++) out[(size_t)pos * NCLS + c] = z[c] * inv;
    }
}

extern "C" void kernel_launch(void* const* d_in, const int* in_sizes, int n_in,
                              void* d_out, int out_size)
{
    const int*   tokens = (const int*)d_in[0];
    const float* emb    = (const float*)d_in[1];
    const float* Wf     = (const float*)d_in[2];
    const float* Uf     = (const float*)d_in[3];
    const float* bf     = (const float*)d_in[4];
    const float* Wb     = (const float*)d_in[5];
    const float* Ub     = (const float*)d_in[6];
    const float* bb     = (const float*)d_in[7];
    const float* gamma  = (const float*)d_in[8];
    const float* beta   = (const float*)d_in[9];
    const float* mmean  = (const float*)d_in[10];
    const float* mvar   = (const float*)d_in[11];
    const float* Wd     = (const float*)d_in[12];
    const float* bd     = (const float*)d_in[13];
    float* out = (float*)d_out;

    static bool attr_done = false;
    if (!attr_done) {
        cudaFuncSetAttribute(lstm_kernel, cudaFuncAttributeMaxDynamicSharedMemorySize, 219392);
        attr_done = true;
    }

    utrans_kernel<<<128, 512>>>(Uf, Ub);
    headprep_kernel<<<1, 256>>>(gamma, beta, mmean, mvar, Wd, bd);
    proj_kernel<<<235 * 8 * 2, 256>>>(emb, Wf, bf, Wb, bb);
    lstm_kernel<<<128, 256, 219392>>>(tokens);
    head_kernel<<<BSZ * TT / 8, 256>>>(out);
}